// round 11
// baseline (speedup 1.0000x reference)
#include <cuda_runtime.h>
#include <stdint.h>

// Problem constants (fixed shapes from reference: B=8, K=4, N=131072)
#define T_TOTAL   4194304      // B*K*N
#define TILE      4096         // elements per block (8 warps x 512)
#define NBLK      1024         // T_TOTAL / TILE
#define NT        256          // threads per block
#define NWARP     (T_TOTAL / 512)   // 8192 warp-chunks
#define NEG_IDLE_F (-100000000.0f)
#define NEG_FILL_F (-1000.0f)

// Scratch (device globals — no allocation allowed in kernel_launch)
__device__ unsigned g_wsum[NWARP];            // packed per-warp sums (s | a<<16)
__device__ int      g_woff_s[NWARP];          // per-warp global exclusive offsets
__device__ int      g_woff_a[NWARP];
__device__ unsigned g_packed[T_TOTAL / 16];   // 1MB: 16 surf bits | 16 air bits

// ---------------------------------------------------------------------------
// Kernel 1: read both masks once, bit-pack to 1MB scratch, per-WARP sums.
// No shared memory, no barriers.
// ---------------------------------------------------------------------------
__global__ __launch_bounds__(NT) void k_pack(const uint32_t* __restrict__ ms,
                                             const uint32_t* __restrict__ ma) {
    int blk = blockIdx.x, tid = threadIdx.x;
    int lane = tid & 31, w = tid >> 5;
    size_t e0 = (size_t)blk * TILE + (size_t)tid * 16;
    const uint4* s4 = reinterpret_cast<const uint4*>(ms + e0);
    const uint4* a4 = reinterpret_cast<const uint4*>(ma + e0);

    unsigned bits_s = 0, bits_a = 0;
    #pragma unroll
    for (int i = 0; i < 4; i++) {
        uint4 s = s4[i];
        uint4 a = a4[i];
        bits_s |= ((s.x != 0u) << (i * 4)) | ((s.y != 0u) << (i * 4 + 1)) |
                  ((s.z != 0u) << (i * 4 + 2)) | ((s.w != 0u) << (i * 4 + 3));
        bits_a |= ((a.x != 0u) << (i * 4)) | ((a.y != 0u) << (i * 4 + 1)) |
                  ((a.z != 0u) << (i * 4 + 2)) | ((a.w != 0u) << (i * 4 + 3));
    }
    g_packed[blk * NT + tid] = bits_s | (bits_a << 16);

    // Packed warp reduce (fields <= 512 < 2^16).
    int p = __popc(bits_s) | (__popc(bits_a) << 16);
    #pragma unroll
    for (int o = 16; o > 0; o >>= 1)
        p += __shfl_xor_sync(0xffffffffu, p, o);
    if (lane == 0) g_wsum[blk * 8 + w] = (unsigned)p;
}

// ---------------------------------------------------------------------------
// Kernel 2: exclusive scan of 8192 packed warp sums -> per-warp offsets.
// One block, 1024 threads, 8 entries each (sequential local scan + block scan).
// ---------------------------------------------------------------------------
__global__ __launch_bounds__(1024) void k_scan() {
    int tid = threadIdx.x, lane = tid & 31, w = tid >> 5;
    int ls[8], la_[8];
    int ss = 0, sa = 0;
    #pragma unroll
    for (int i = 0; i < 8; i++) {
        unsigned pw = g_wsum[tid * 8 + i];
        ls[i] = ss; la_[i] = sa;
        ss += (int)(pw & 0xffffu);
        sa += (int)(pw >> 16);
    }
    // Block exclusive scan of (ss, sa).
    int is = ss, ia = sa;
    #pragma unroll
    for (int o = 1; o < 32; o <<= 1) {
        int t = __shfl_up_sync(0xffffffffu, is, o); if (lane >= o) is += t;
        t     = __shfl_up_sync(0xffffffffu, ia, o); if (lane >= o) ia += t;
    }
    __shared__ int ws[32], wa[32];
    if (lane == 31) { ws[w] = is; wa[w] = ia; }
    __syncthreads();
    if (w == 0) {
        int ts = ws[lane], ta = wa[lane];
        int js = ts, ja = ta;
        #pragma unroll
        for (int o = 1; o < 32; o <<= 1) {
            int t = __shfl_up_sync(0xffffffffu, js, o); if (lane >= o) js += t;
            t     = __shfl_up_sync(0xffffffffu, ja, o); if (lane >= o) ja += t;
        }
        ws[lane] = js - ts;
        wa[lane] = ja - ta;
    }
    __syncthreads();
    int base_s = ws[w] + is - ss;
    int base_a = wa[w] + ia - sa;
    #pragma unroll
    for (int i = 0; i < 8; i++) {
        g_woff_s[tid * 8 + i] = base_s + ls[i];
        g_woff_a[tid * 8 + i] = base_a + la_[i];
    }
}

// ---------------------------------------------------------------------------
// Kernel 3: expand/gather/write. BARRIER-FREE: warp-autonomous.
// Warp owns 512 contiguous elems. One coalesced load of 32 packed words,
// ONE byte-packed shfl scan covering all 4 iterations x both masks
// (per-byte inclusive sums <= 128 -> no carries), then gathers + stores.
// ---------------------------------------------------------------------------
__global__ __launch_bounds__(NT) void k_main(
    const float* __restrict__ rgb, const float* __restrict__ ls,
    const float* __restrict__ la,  const float* __restrict__ idle_st,
    float* __restrict__ rgb_out, float* __restrict__ ls_out,
    float* __restrict__ la_out) {

    int blk = blockIdx.x, tid = threadIdx.x;
    int lane = tid & 31, w = tid >> 5;
    int gw = blk * 8 + w;

    // Warp's 32 packed words in one 128B coalesced load.
    unsigned wbits = g_packed[gw * 32 + lane];

    float idle   = idle_st[blk >> 5];  // 32 tiles per (b,k) row
    float scale  = 1.0f - idle;
    float negadd = idle * NEG_IDLE_F;

    // Distribute words: iter j, lane l needs word j*8 + (l>>2).
    unsigned ms4[4], ma4[4];
    unsigned shift = (lane & 3) * 4;
    unsigned cnt_s = 0, cnt_a = 0;     // byte j = count for iter j
    #pragma unroll
    for (int j = 0; j < 4; j++) {
        unsigned word = __shfl_sync(0xffffffffu, wbits, j * 8 + (lane >> 2));
        ms4[j] = (word >> shift) & 0xFu;
        ma4[j] = (word >> (16 + shift)) & 0xFu;
        cnt_s |= __popc(ms4[j]) << (j * 8);
        cnt_a |= __popc(ma4[j]) << (j * 8);
    }

    // Single inclusive warp scan, byte-parallel (max byte sum 128 < 256).
    unsigned ip_s = cnt_s, ip_a = cnt_a;
    #pragma unroll
    for (int o = 1; o < 32; o <<= 1) {
        unsigned ts = __shfl_up_sync(0xffffffffu, ip_s, o);
        unsigned ta = __shfl_up_sync(0xffffffffu, ip_a, o);
        if (lane >= o) { ip_s += ts; ip_a += ta; }
    }
    unsigned tot_s = __shfl_sync(0xffffffffu, ip_s, 31);
    unsigned tot_a = __shfl_sync(0xffffffffu, ip_a, 31);
    unsigned ep_s = ip_s - cnt_s;      // exclusive, per byte
    unsigned ep_a = ip_a - cnt_a;

    // Per-iter warp base offsets (prefix over iter totals).
    int run_s = g_woff_s[gw];
    int run_a = g_woff_a[gw];
    int ibase_s[4], ibase_a[4];
    {
        int cs = 0, ca = 0;
        #pragma unroll
        for (int j = 0; j < 4; j++) {
            ibase_s[j] = run_s + cs;
            ibase_a[j] = run_a + ca;
            cs += (int)((tot_s >> (j * 8)) & 0xffu);
            ca += (int)((tot_a >> (j * 8)) & 0xffu);
        }
    }

    size_t wbase = (size_t)blk * TILE + (size_t)w * 512;

    #pragma unroll
    for (int j = 0; j < 4; j++) {
        size_t e0 = wbase + j * 128 + lane * 4;
        int base_s = ibase_s[j] + (int)((ep_s >> (j * 8)) & 0xffu);
        int base_a = ibase_a[j] + (int)((ep_a >> (j * 8)) & 0xffu);
        unsigned mS = ms4[j], mA = ma4[j];

        float os[4], oa[4], ro[12];
        #pragma unroll
        for (int q = 0; q < 4; q++) {
            if ((mS >> q) & 1u) {
                int idx = base_s + __popc(mS & ((1u << q) - 1u));
                os[q] = __ldg(ls + idx) * scale + negadd;
                const float* rp = rgb + (size_t)idx * 3;
                ro[q * 3 + 0] = rp[0] * scale;
                ro[q * 3 + 1] = rp[1] * scale;
                ro[q * 3 + 2] = rp[2] * scale;
            } else {
                os[q] = NEG_FILL_F;
                ro[q * 3 + 0] = 0.0f; ro[q * 3 + 1] = 0.0f; ro[q * 3 + 2] = 0.0f;
            }
            if ((mA >> q) & 1u) {
                int idx = base_a + __popc(mA & ((1u << q) - 1u));
                oa[q] = __ldg(la + idx) * scale + negadd;
            } else {
                oa[q] = NEG_FILL_F;
            }
        }

        // Coalesced 16B stores (warp: 512B contiguous for ls/la, 1.5KB for rgb).
        *reinterpret_cast<float4*>(ls_out + e0) = make_float4(os[0], os[1], os[2], os[3]);
        *reinterpret_cast<float4*>(la_out + e0) = make_float4(oa[0], oa[1], oa[2], oa[3]);
        float4* rout = reinterpret_cast<float4*>(rgb_out + e0 * 3);
        rout[0] = make_float4(ro[0], ro[1],  ro[2],  ro[3]);
        rout[1] = make_float4(ro[4], ro[5],  ro[6],  ro[7]);
        rout[2] = make_float4(ro[8], ro[9],  ro[10], ro[11]);
    }
}

// ---------------------------------------------------------------------------
// Launch: 3 kernels (pack+warp sums, scan, barrier-free expand).
// ---------------------------------------------------------------------------
extern "C" void kernel_launch(void* const* d_in, const int* in_sizes, int n_in,
                              void* d_out, int out_size) {
    const float*    rgb  = (const float*)d_in[0];
    const float*    ls   = (const float*)d_in[1];
    const float*    la   = (const float*)d_in[2];
    const uint32_t* msf  = (const uint32_t*)d_in[3];
    const uint32_t* maf  = (const uint32_t*)d_in[4];
    const float*    idle = (const float*)d_in[5];

    float* out     = (float*)d_out;
    float* rgb_out = out;
    float* ls_out  = out + (size_t)T_TOTAL * 3;
    float* la_out  = ls_out + T_TOTAL;

    k_pack<<<NBLK, NT>>>(msf, maf);
    k_scan<<<1, 1024>>>();
    k_main<<<NBLK, NT>>>(rgb, ls, la, idle, rgb_out, ls_out, la_out);
}